// round 11
// baseline (speedup 1.0000x reference)
#include <cuda_runtime.h>
#include <math.h>

#define NBATCH 4
#define NHID   128
#define NCOL   65536
#define NMODE  256
#define NHS    8          // h-split for kmodes

// Scratch (allocation-free rule: device globals)
__device__ __align__(16) float g_yp[NHS * 2 * NBATCH * NHID * NMODE]; // 32 MB partials
__device__ __align__(16) float g_y[2 * NBATCH * NHID * NMODE];        // 1 MB reduced
__device__ __align__(16) float g_c[NHID * NMODE];                     // c + lin_b (raw)

__device__ __forceinline__ float gelu_exact(float v) {
    return 0.5f * v * (1.0f + erff(v * 0.70710678118654752440f));
}

// ---- packed f32x2 helpers (SASS FFMA2; PTX-only path on sm_103a) ----------
__device__ __forceinline__ unsigned long long pack2_dup(float v) {
    unsigned long long r;
    unsigned int u = __float_as_uint(v);
    asm("mov.b64 %0, {%1, %1};" : "=l"(r) : "r"(u));
    return r;
}
__device__ __forceinline__ void fma2(unsigned long long& d,
                                     unsigned long long a, unsigned long long b) {
    asm("fma.rn.f32x2 %0, %1, %2, %0;" : "+l"(d) : "l"(a), "l"(b));
}
__device__ __forceinline__ float2 unpack2(unsigned long long v) {
    unsigned int lo, hi;
    asm("mov.b64 {%0, %1}, %2;" : "=r"(lo), "=r"(hi) : "l"(v));
    return make_float2(__uint_as_float(lo), __uint_as_float(hi));
}

// ---------------------------------------------------------------------------
// Kernel A (measured 17.2us): per-mode GEMM, h split 8 ways.
//  g_yp[hs][ri][b][k][m] = sum_{h in chunk} x[b,h,m] * w_{ri}[h,k,m]
// grid (64 = 8 kb * 8 hs, 8 mb, 2 ri) = 1024 CTAs, 128 threads.
// ---------------------------------------------------------------------------
__global__ void __launch_bounds__(128) kmodes(const float* __restrict__ x,
                                              const float* __restrict__ wr,
                                              const float* __restrict__ wi) {
    __shared__ float xs[NBATCH * 16 * 32];    // 8 KB
    const int kb = blockIdx.x >> 3, hs = blockIdx.x & 7;
    const int mb = blockIdx.y, ri = blockIdx.z;
    const float* w = ri ? wi : wr;
    const int m0 = mb * 32, k0 = kb * 16, h0 = hs * 16;
    const int tid = threadIdx.x;

    for (int i = tid; i < NBATCH * 16 * 8; i += 128) {
        int j = i & 7;
        int bh = i >> 3;                 // b*16 + h
        int b = bh >> 4, h = bh & 15;
        float4 v = *reinterpret_cast<const float4*>(
            x + (size_t)(b * NHID + h0 + h) * NCOL + m0 + j * 4);
        *reinterpret_cast<float4*>(xs + bh * 32 + j * 4) = v;
    }
    __syncthreads();

    const int kl = tid & 15;      // 16 k per CTA
    const int mg = tid >> 4;      // 8 m-quads
    const int k  = k0 + kl;
    const int mm = mg * 4;

    float a[NBATCH][4];
#pragma unroll
    for (int b = 0; b < NBATCH; b++)
#pragma unroll
        for (int j = 0; j < 4; j++) a[b][j] = 0.f;

    const float* wp = w + (size_t)h0 * NHID * NMODE + (size_t)k * NMODE + m0 + mm;
#pragma unroll 8
    for (int h = 0; h < 16; h++) {
        float4 wv = __ldg(reinterpret_cast<const float4*>(wp + (size_t)h * NHID * NMODE));
#pragma unroll
        for (int b = 0; b < NBATCH; b++) {
            float4 xv = *reinterpret_cast<const float4*>(xs + (b * 16 + h) * 32 + mm);
            a[b][0] += xv.x * wv.x;
            a[b][1] += xv.y * wv.y;
            a[b][2] += xv.z * wv.z;
            a[b][3] += xv.w * wv.w;
        }
    }
#pragma unroll
    for (int b = 0; b < NBATCH; b++) {
        float4 v = make_float4(a[b][0], a[b][1], a[b][2], a[b][3]);
        *reinterpret_cast<float4*>(
            &g_yp[(((hs * 2 + ri) * NBATCH + b) * NHID + k) * NMODE + m0 + mm]) = v;
    }
}

// ---------------------------------------------------------------------------
// Kernel R: reduce the 8 h-partials (36 MB streamed, MLP=8).
// ---------------------------------------------------------------------------
__global__ void __launch_bounds__(256) kreduce() {
    const int i4 = blockIdx.x * 256 + threadIdx.x;     // float4 index
    const int STRIDE4 = 2 * NBATCH * NHID * NMODE / 4; // 65536 float4 per slice
    float4 v[NHS];
#pragma unroll
    for (int s = 0; s < NHS; s++)
        v[s] = *reinterpret_cast<const float4*>(&g_yp[(s * STRIDE4 + i4) * 4]);
    float4 acc = v[0];
#pragma unroll
    for (int s = 1; s < NHS; s++) {
        acc.x += v[s].x; acc.y += v[s].y; acc.z += v[s].z; acc.w += v[s].w;
    }
    *reinterpret_cast<float4*>(&g_y[i4 * 4]) = acc;
}

// ---------------------------------------------------------------------------
// Kernel B: c[k,n] = sum_h lin_w[k,h]*bias[h,n], FFMA2 paired along n.
// Weights pre-duplicated in smem (no in-loop movs); bias pairs load natively.
//   n >= 256: out[b,k,n,(0,1)] = (gelu(c+lin_b[k]), 0) for all 4 b
//   n <  256: g_c[k,n] = c + lin_b[k]
// grid (1024 nb of 64 cols, 4 kb of 32) = 4096 CTAs, 128 threads
// (8 kt x 16 nt), per thread 4k x 4n (n cols {nt*2, nt*2+1, +32}).
// smem 67.6 KB -> 3 CTAs/SM. Epilogue stores fully coalesced (256B runs).
// ---------------------------------------------------------------------------
#define WDPITCH 34   // wdup row pitch in ull (EVEN -> 16B-aligned LDS.128 rows)
__global__ void __launch_bounds__(128) kmain(const float* __restrict__ bias,
                                             const float* __restrict__ lin_w,
                                             const float* __restrict__ lin_b,
                                             float* __restrict__ out) {
    extern __shared__ float sm[];
    unsigned long long* wdup = reinterpret_cast<unsigned long long*>(sm); // [h][32k] pitch 34
    float* sb = sm + NHID * WDPITCH * 2;   // [h][64]  (wdup = 128*34 ull = 8704 floats)
    __shared__ float slb[32];

    const int tid = threadIdx.x;
    const int n_base = blockIdx.x * 64;
    const int kbase  = blockIdx.y * 32;

    // stage lin_w duplicated: wdup[h][k] = (w,w); coalesced LDG
    for (int i = tid; i < 32 * NHID; i += 128) {
        int h = i & 127, k = i >> 7;
        wdup[h * WDPITCH + k] = pack2_dup(lin_w[(kbase + k) * NHID + h]);
    }
    if (tid < 32) slb[tid] = lin_b[kbase + tid];
    // stage bias tile [h][64], conflict-free
    for (int i = tid; i < NHID * 16; i += 128) {
        int h = i >> 4, j = i & 15;
        float4 v = *reinterpret_cast<const float4*>(bias + (size_t)h * NCOL + n_base + j * 4);
        *reinterpret_cast<float4*>(sb + h * 64 + j * 4) = v;
    }
    __syncthreads();

    const int kt = tid >> 4;     // 0..7  -> 4 k each
    const int nt = tid & 15;     // 0..15 -> n cols {nt*2, nt*2+1} and {+32}

    unsigned long long acc2[4][2];   // [k][n-block]; lanes = (n, n+1)
#pragma unroll
    for (int p = 0; p < 4; p++) { acc2[p][0] = 0ULL; acc2[p][1] = 0ULL; }

    const unsigned long long* wrow = wdup + kt * 4;   // (h*34 + kt*4) even -> 16B aligned
    const float* bpA = sb + nt * 2;
    const float* bpB = sb + 32 + nt * 2;
#pragma unroll 4
    for (int h = 0; h < NHID; h++) {
        ulonglong2 w01 = *reinterpret_cast<const ulonglong2*>(wrow + h * WDPITCH);
        ulonglong2 w23 = *reinterpret_cast<const ulonglong2*>(wrow + h * WDPITCH + 2);
        unsigned long long bA = *reinterpret_cast<const unsigned long long*>(bpA + h * 64);
        unsigned long long bB = *reinterpret_cast<const unsigned long long*>(bpB + h * 64);
        fma2(acc2[0][0], w01.x, bA); fma2(acc2[0][1], w01.x, bB);
        fma2(acc2[1][0], w01.y, bA); fma2(acc2[1][1], w01.y, bB);
        fma2(acc2[2][0], w23.x, bA); fma2(acc2[2][1], w23.x, bB);
        fma2(acc2[3][0], w23.y, bA); fma2(acc2[3][1], w23.y, bB);
    }

    const int nA = n_base + nt * 2;
    if (n_base >= NMODE) {
#pragma unroll
        for (int p = 0; p < 4; p++) {
            const int k = kbase + kt * 4 + p;
            const float lb = slb[kt * 4 + p];
            float2 aA = unpack2(acc2[p][0]);
            float2 aB = unpack2(acc2[p][1]);
            float4 vA = make_float4(gelu_exact(aA.x + lb), 0.f, gelu_exact(aA.y + lb), 0.f);
            float4 vB = make_float4(gelu_exact(aB.x + lb), 0.f, gelu_exact(aB.y + lb), 0.f);
#pragma unroll
            for (int b = 0; b < NBATCH; b++) {
                float* op = out + 2 * ((size_t)(b * NHID + k) * NCOL + nA);
                __stcs(reinterpret_cast<float4*>(op),      vA);
                __stcs(reinterpret_cast<float4*>(op + 64), vB);   // +32 n = +64 floats
            }
        }
    } else {
#pragma unroll
        for (int p = 0; p < 4; p++) {
            const int k = kbase + kt * 4 + p;
            const float lb = slb[kt * 4 + p];
            float2 aA = unpack2(acc2[p][0]);
            float2 aB = unpack2(acc2[p][1]);
            *reinterpret_cast<float2*>(&g_c[k * NMODE + nA])      = make_float2(aA.x + lb, aA.y + lb);
            *reinterpret_cast<float2*>(&g_c[k * NMODE + nA + 32]) = make_float2(aB.x + lb, aB.y + lb);
        }
    }
}

// ---------------------------------------------------------------------------
// Kernel C: n < 256 region, reads reduced g_y (1 MB, L2-hot).
//   out[b,k,n,(0,1)] = (gelu(t_r + g_c[k,n]), gelu(t_i))
// grid (16 mt of 16, 4 b, 8 kb of 16) = 512 CTAs, 256 threads, 1 (k,n)/thread.
// ---------------------------------------------------------------------------
__global__ void __launch_bounds__(256) ksmall(const float* __restrict__ lin_w,
                                              float* __restrict__ out) {
    __shared__ float sW[16 * 129];      // [k(16)][h] pitch 129
    __shared__ float sy[2 * NHID * 16]; // [ri*128+h][16]
    const int mt = blockIdx.x, b = blockIdx.y, kb = blockIdx.z;
    const int tid = threadIdx.x;
    const int m0 = mt * 16;

    for (int i = tid; i < 16 * NHID; i += 256) {
        int h = i & 127, r = i >> 7;
        sW[r * 129 + h] = lin_w[(kb * 16 + r) * NHID + h];
    }
    for (int i = tid; i < 2 * NHID * 4; i += 256) {     // 1024 float4
        int j = i & 3;
        int rh = i >> 2;                 // ri*128 + h
        int ri = rh >> 7, h = rh & 127;
        float4 v = *reinterpret_cast<const float4*>(
            &g_y[((ri * NBATCH + b) * NHID + h) * NMODE + m0 + j * 4]);
        *reinterpret_cast<float4*>(sy + rh * 16 + j * 4) = v;
    }
    __syncthreads();

    const int kl = tid >> 4;   // 0..15
    const int ng = tid & 15;   // 0..15
    const int k = kb * 16 + kl;
    const int n = m0 + ng;

    float ar = 0.f, ai = 0.f;
    const float* wp  = sW + kl * 129;
    const float* yrp = sy + ng;
    const float* yip = sy + NHID * 16 + ng;
#pragma unroll 8
    for (int h = 0; h < NHID; h++) {
        float w = wp[h];
        ar += w * yrp[h * 16];
        ai += w * yip[h * 16];
    }
    float cv = g_c[k * NMODE + n];
    float2 o = make_float2(gelu_exact(ar + cv), gelu_exact(ai));
    *reinterpret_cast<float2*>(out + 2 * ((size_t)(b * NHID + k) * NCOL + n)) = o;
}

// ---------------------------------------------------------------------------
extern "C" void kernel_launch(void* const* d_in, const int* in_sizes, int n_in,
                              void* d_out, int out_size) {
    const float* x     = (const float*)d_in[0];
    const float* wr    = (const float*)d_in[1];
    const float* wi    = (const float*)d_in[2];
    const float* bias  = (const float*)d_in[3];
    const float* lin_w = (const float*)d_in[4];
    const float* lin_b = (const float*)d_in[5];
    float* out = (float*)d_out;

    (void)in_sizes; (void)n_in; (void)out_size;

    const int kmain_smem = NHID * WDPITCH * 8 + NHID * 64 * 4;  // 34816 + 32768 = 67584 B
    cudaFuncSetAttribute(kmain, cudaFuncAttributeMaxDynamicSharedMemorySize, kmain_smem);

    kmodes<<<dim3(64, 8, 2), 128>>>(x, wr, wi);
    kreduce<<<256, 256>>>();
    kmain<<<dim3(1024, 4), 128, kmain_smem>>>(bias, lin_w, lin_b, out);
    ksmall<<<dim3(16, 4, 8), 256>>>(lin_w, out);
}

// round 12
// speedup vs baseline: 1.0086x; 1.0086x over previous
#include <cuda_runtime.h>
#include <math.h>

#define NBATCH 4
#define NHID   128
#define NCOL   65536
#define NMODE  256
#define NHS    8          // h-split for kmodes

// Scratch (allocation-free rule: device globals)
__device__ __align__(16) float g_yp[NHS * 2 * NBATCH * NHID * NMODE]; // 32 MB partials
__device__ __align__(16) float g_y[2 * NBATCH * NHID * NMODE];        // 1 MB reduced
__device__ __align__(16) float g_c[NHID * NMODE];                     // c + lin_b (raw)

__device__ __forceinline__ float gelu_exact(float v) {
    return 0.5f * v * (1.0f + erff(v * 0.70710678118654752440f));
}

// ---- packed f32x2 helpers (SASS FFMA2; PTX-only path on sm_103a) ----------
__device__ __forceinline__ unsigned long long pack2_dup(float v) {
    unsigned long long r;
    unsigned int u = __float_as_uint(v);
    asm("mov.b64 %0, {%1, %1};" : "=l"(r) : "r"(u));
    return r;
}
__device__ __forceinline__ void fma2(unsigned long long& d,
                                     unsigned long long a, unsigned long long b) {
    asm("fma.rn.f32x2 %0, %1, %2, %0;" : "+l"(d) : "l"(a), "l"(b));
}
__device__ __forceinline__ float2 unpack2(unsigned long long v) {
    unsigned int lo, hi;
    asm("mov.b64 {%0, %1}, %2;" : "=r"(lo), "=r"(hi) : "l"(v));
    return make_float2(__uint_as_float(lo), __uint_as_float(hi));
}

// ---------------------------------------------------------------------------
// Kernel A (measured 17.2us): per-mode GEMM, h split 8 ways.
//  g_yp[hs][ri][b][k][m] = sum_{h in chunk} x[b,h,m] * w_{ri}[h,k,m]
// grid (64 = 8 kb * 8 hs, 8 mb, 2 ri) = 1024 CTAs, 128 threads.
// ---------------------------------------------------------------------------
__global__ void __launch_bounds__(128) kmodes(const float* __restrict__ x,
                                              const float* __restrict__ wr,
                                              const float* __restrict__ wi) {
    __shared__ float xs[NBATCH * 16 * 32];    // 8 KB
    const int kb = blockIdx.x >> 3, hs = blockIdx.x & 7;
    const int mb = blockIdx.y, ri = blockIdx.z;
    const float* w = ri ? wi : wr;
    const int m0 = mb * 32, k0 = kb * 16, h0 = hs * 16;
    const int tid = threadIdx.x;

    for (int i = tid; i < NBATCH * 16 * 8; i += 128) {
        int j = i & 7;
        int bh = i >> 3;                 // b*16 + h
        int b = bh >> 4, h = bh & 15;
        float4 v = *reinterpret_cast<const float4*>(
            x + (size_t)(b * NHID + h0 + h) * NCOL + m0 + j * 4);
        *reinterpret_cast<float4*>(xs + bh * 32 + j * 4) = v;
    }
    __syncthreads();

    const int kl = tid & 15;      // 16 k per CTA
    const int mg = tid >> 4;      // 8 m-quads
    const int k  = k0 + kl;
    const int mm = mg * 4;

    float a[NBATCH][4];
#pragma unroll
    for (int b = 0; b < NBATCH; b++)
#pragma unroll
        for (int j = 0; j < 4; j++) a[b][j] = 0.f;

    const float* wp = w + (size_t)h0 * NHID * NMODE + (size_t)k * NMODE + m0 + mm;
#pragma unroll 8
    for (int h = 0; h < 16; h++) {
        float4 wv = __ldg(reinterpret_cast<const float4*>(wp + (size_t)h * NHID * NMODE));
#pragma unroll
        for (int b = 0; b < NBATCH; b++) {
            float4 xv = *reinterpret_cast<const float4*>(xs + (b * 16 + h) * 32 + mm);
            a[b][0] += xv.x * wv.x;
            a[b][1] += xv.y * wv.y;
            a[b][2] += xv.z * wv.z;
            a[b][3] += xv.w * wv.w;
        }
    }
#pragma unroll
    for (int b = 0; b < NBATCH; b++) {
        float4 v = make_float4(a[b][0], a[b][1], a[b][2], a[b][3]);
        *reinterpret_cast<float4*>(
            &g_yp[(((hs * 2 + ri) * NBATCH + b) * NHID + k) * NMODE + m0 + mm]) = v;
    }
}

// ---------------------------------------------------------------------------
// Kernel R: reduce the 8 h-partials (36 MB streamed, MLP=8).
// ---------------------------------------------------------------------------
__global__ void __launch_bounds__(256) kreduce() {
    const int i4 = blockIdx.x * 256 + threadIdx.x;     // float4 index
    const int STRIDE4 = 2 * NBATCH * NHID * NMODE / 4; // 65536 float4 per slice
    float4 v[NHS];
#pragma unroll
    for (int s = 0; s < NHS; s++)
        v[s] = *reinterpret_cast<const float4*>(&g_yp[(s * STRIDE4 + i4) * 4]);
    float4 acc = v[0];
#pragma unroll
    for (int s = 1; s < NHS; s++) {
        acc.x += v[s].x; acc.y += v[s].y; acc.z += v[s].z; acc.w += v[s].w;
    }
    *reinterpret_cast<float4*>(&g_y[i4 * 4]) = acc;
}

// ---------------------------------------------------------------------------
// Kernel B: c[k,n] = sum_h lin_w[k,h]*bias[h,n], FFMA2 paired along n.
// Weights pre-duplicated in smem (no in-loop movs); bias pairs load natively.
//   n >= 256: out[b,k,n,(0,1)] = (gelu(c+lin_b[k]), 0) for all 4 b
//   n <  256: g_c[k,n] = c + lin_b[k]
// grid (1024 nb of 64 cols, 4 kb of 32) = 4096 CTAs, 128 threads
// (8 kt x 16 nt), per thread 4k x 4n (n cols {nt*2, nt*2+1, +32}).
// smem 67.6 KB -> 3 CTAs/SM. Epilogue stores fully coalesced (256B runs).
// ---------------------------------------------------------------------------
#define WDPITCH 34   // wdup row pitch in ull (EVEN -> 16B-aligned LDS.128 rows)
__global__ void __launch_bounds__(128) kmain(const float* __restrict__ bias,
                                             const float* __restrict__ lin_w,
                                             const float* __restrict__ lin_b,
                                             float* __restrict__ out) {
    extern __shared__ float sm[];
    unsigned long long* wdup = reinterpret_cast<unsigned long long*>(sm); // [h][32k] pitch 34
    float* sb = sm + NHID * WDPITCH * 2;   // [h][64]  (wdup = 128*34 ull = 8704 floats)
    __shared__ float slb[32];

    const int tid = threadIdx.x;
    const int n_base = blockIdx.x * 64;
    const int kbase  = blockIdx.y * 32;

    // stage lin_w duplicated: wdup[h][k] = (w,w); coalesced LDG
    for (int i = tid; i < 32 * NHID; i += 128) {
        int h = i & 127, k = i >> 7;
        wdup[h * WDPITCH + k] = pack2_dup(lin_w[(kbase + k) * NHID + h]);
    }
    if (tid < 32) slb[tid] = lin_b[kbase + tid];
    // stage bias tile [h][64], conflict-free
    for (int i = tid; i < NHID * 16; i += 128) {
        int h = i >> 4, j = i & 15;
        float4 v = *reinterpret_cast<const float4*>(bias + (size_t)h * NCOL + n_base + j * 4);
        *reinterpret_cast<float4*>(sb + h * 64 + j * 4) = v;
    }
    __syncthreads();

    const int kt = tid >> 4;     // 0..7  -> 4 k each
    const int nt = tid & 15;     // 0..15 -> n cols {nt*2, nt*2+1} and {+32}

    unsigned long long acc2[4][2];   // [k][n-block]; lanes = (n, n+1)
#pragma unroll
    for (int p = 0; p < 4; p++) { acc2[p][0] = 0ULL; acc2[p][1] = 0ULL; }

    const unsigned long long* wrow = wdup + kt * 4;   // (h*34 + kt*4) even -> 16B aligned
    const float* bpA = sb + nt * 2;
    const float* bpB = sb + 32 + nt * 2;
#pragma unroll 4
    for (int h = 0; h < NHID; h++) {
        ulonglong2 w01 = *reinterpret_cast<const ulonglong2*>(wrow + h * WDPITCH);
        ulonglong2 w23 = *reinterpret_cast<const ulonglong2*>(wrow + h * WDPITCH + 2);
        unsigned long long bA = *reinterpret_cast<const unsigned long long*>(bpA + h * 64);
        unsigned long long bB = *reinterpret_cast<const unsigned long long*>(bpB + h * 64);
        fma2(acc2[0][0], w01.x, bA); fma2(acc2[0][1], w01.x, bB);
        fma2(acc2[1][0], w01.y, bA); fma2(acc2[1][1], w01.y, bB);
        fma2(acc2[2][0], w23.x, bA); fma2(acc2[2][1], w23.x, bB);
        fma2(acc2[3][0], w23.y, bA); fma2(acc2[3][1], w23.y, bB);
    }

    const int nA = n_base + nt * 2;
    if (n_base >= NMODE) {
#pragma unroll
        for (int p = 0; p < 4; p++) {
            const int k = kbase + kt * 4 + p;
            const float lb = slb[kt * 4 + p];
            float2 aA = unpack2(acc2[p][0]);
            float2 aB = unpack2(acc2[p][1]);
            float4 vA = make_float4(gelu_exact(aA.x + lb), 0.f, gelu_exact(aA.y + lb), 0.f);
            float4 vB = make_float4(gelu_exact(aB.x + lb), 0.f, gelu_exact(aB.y + lb), 0.f);
#pragma unroll
            for (int b = 0; b < NBATCH; b++) {
                float* op = out + 2 * ((size_t)(b * NHID + k) * NCOL + nA);
                __stcs(reinterpret_cast<float4*>(op),      vA);
                __stcs(reinterpret_cast<float4*>(op + 64), vB);   // +32 n = +64 floats
            }
        }
    } else {
#pragma unroll
        for (int p = 0; p < 4; p++) {
            const int k = kbase + kt * 4 + p;
            const float lb = slb[kt * 4 + p];
            float2 aA = unpack2(acc2[p][0]);
            float2 aB = unpack2(acc2[p][1]);
            *reinterpret_cast<float2*>(&g_c[k * NMODE + nA])      = make_float2(aA.x + lb, aA.y + lb);
            *reinterpret_cast<float2*>(&g_c[k * NMODE + nA + 32]) = make_float2(aB.x + lb, aB.y + lb);
        }
    }
}

// ---------------------------------------------------------------------------
// Kernel C: n < 256 region, reads reduced g_y (1 MB, L2-hot).
//   out[b,k,n,(0,1)] = (gelu(t_r + g_c[k,n]), gelu(t_i))
// grid (16 mt of 16, 4 b, 8 kb of 16) = 512 CTAs, 256 threads, 1 (k,n)/thread.
// ---------------------------------------------------------------------------
__global__ void __launch_bounds__(256) ksmall(const float* __restrict__ lin_w,
                                              float* __restrict__ out) {
    __shared__ float sW[16 * 129];      // [k(16)][h] pitch 129
    __shared__ float sy[2 * NHID * 16]; // [ri*128+h][16]
    const int mt = blockIdx.x, b = blockIdx.y, kb = blockIdx.z;
    const int tid = threadIdx.x;
    const int m0 = mt * 16;

    for (int i = tid; i < 16 * NHID; i += 256) {
        int h = i & 127, r = i >> 7;
        sW[r * 129 + h] = lin_w[(kb * 16 + r) * NHID + h];
    }
    for (int i = tid; i < 2 * NHID * 4; i += 256) {     // 1024 float4
        int j = i & 3;
        int rh = i >> 2;                 // ri*128 + h
        int ri = rh >> 7, h = rh & 127;
        float4 v = *reinterpret_cast<const float4*>(
            &g_y[((ri * NBATCH + b) * NHID + h) * NMODE + m0 + j * 4]);
        *reinterpret_cast<float4*>(sy + rh * 16 + j * 4) = v;
    }
    __syncthreads();

    const int kl = tid >> 4;   // 0..15
    const int ng = tid & 15;   // 0..15
    const int k = kb * 16 + kl;
    const int n = m0 + ng;

    float ar = 0.f, ai = 0.f;
    const float* wp  = sW + kl * 129;
    const float* yrp = sy + ng;
    const float* yip = sy + NHID * 16 + ng;
#pragma unroll 8
    for (int h = 0; h < NHID; h++) {
        float w = wp[h];
        ar += w * yrp[h * 16];
        ai += w * yip[h * 16];
    }
    float cv = g_c[k * NMODE + n];
    float2 o = make_float2(gelu_exact(ar + cv), gelu_exact(ai));
    *reinterpret_cast<float2*>(out + 2 * ((size_t)(b * NHID + k) * NCOL + n)) = o;
}

// ---------------------------------------------------------------------------
extern "C" void kernel_launch(void* const* d_in, const int* in_sizes, int n_in,
                              void* d_out, int out_size) {
    const float* x     = (const float*)d_in[0];
    const float* wr    = (const float*)d_in[1];
    const float* wi    = (const float*)d_in[2];
    const float* bias  = (const float*)d_in[3];
    const float* lin_w = (const float*)d_in[4];
    const float* lin_b = (const float*)d_in[5];
    float* out = (float*)d_out;

    (void)in_sizes; (void)n_in; (void)out_size;

    const int kmain_smem = NHID * WDPITCH * 8 + NHID * 64 * 4;  // 34816 + 32768 = 67584 B
    cudaFuncSetAttribute(kmain, cudaFuncAttributeMaxDynamicSharedMemorySize, kmain_smem);

    kmodes<<<dim3(64, 8, 2), 128>>>(x, wr, wi);
    kreduce<<<256, 256>>>();
    kmain<<<dim3(1024, 4), 128, kmain_smem>>>(bias, lin_w, lin_b, out);
    ksmall<<<dim3(16, 4, 8), 256>>>(lin_w, out);
}